// round 12
// baseline (speedup 1.0000x reference)
#include <cuda_runtime.h>
#include <cuda_bf16.h>
#include <cuda_fp16.h>
#include <math.h>
#include <stdint.h>

#define NN 50000
#define NF 512
#define NH 512
#define NS 256
#define NC 64
#define NE 1600000
#define KDIM 512
#define SPLIT 24960        // 195 * 128, row split for pipelining

// ---------------- scratch ----------------
static __device__ __half g_bufC[(size_t)NN * NH];   // GEMM1/GEMM3 out
static __device__ __half g_bufD[(size_t)NN * NH];   // GEMM2 out (ping-pong)
static __device__ __half g_A[(size_t)NN * KDIM];    // activations fp16
static __device__ __half g_B1[NH * KDIM];
static __device__ __half g_B2[NH * KDIM];
static __device__ __half g_B3[NS * KDIM];
static __device__ int   g_counts[NN];
static __device__ int   g_rowptr[NN + 1];
static __device__ int   g_cursor[NN];
static __device__ int   g_csr_src[NE];
static __device__ float g_csr_val[NE];
static __device__ float g_ssf_sp[NS * NC];
static __device__ float g_colsq[NC];
static __device__ float g_cn[NC];

#define SWZ(o) ((o) ^ (((o) >> 3) & 0x70))

__device__ __forceinline__ uint32_t smem_u32(const void* p) {
    uint32_t a;
    asm("{ .reg .u64 t; cvta.to.shared.u64 t, %1; cvt.u32.u64 %0, t; }" : "=r"(a) : "l"(p));
    return a;
}

// ---------------- stream/event resources ----------------
struct SideRes {
    cudaStream_t s2 = nullptr;
    cudaEvent_t eFork = nullptr, eW1 = nullptr, eCSR = nullptr, eW23 = nullptr, eSSF = nullptr;
    cudaEvent_t eS1lo = nullptr, eG2hi = nullptr, eS2lo = nullptr, eG3hi = nullptr;
    bool ok = false;
    SideRes() {
        bool o = cudaStreamCreateWithFlags(&s2, cudaStreamNonBlocking) == cudaSuccess;
        cudaEvent_t* evs[9] = {&eFork, &eW1, &eCSR, &eW23, &eSSF, &eS1lo, &eG2hi, &eS2lo, &eG3hi};
        for (int i = 0; i < 9 && o; i++)
            o = cudaEventCreateWithFlags(evs[i], cudaEventDisableTiming) == cudaSuccess;
        ok = o;
    }
};
static SideRes g_res;

// ---------------- CSR build ----------------
__global__ void k_zero_counts() {
    int i = blockIdx.x * blockDim.x + threadIdx.x;
    if (i < NN) g_counts[i] = 0;
}
__global__ void k_count(const int* __restrict__ dst) {
    int e = blockIdx.x * blockDim.x + threadIdx.x;
    if (e < NE) atomicAdd(&g_counts[dst[e]], 1);
}
// parallel exclusive scan over g_counts: 1024 threads, warp-shuffle hierarchy
__global__ void k_scan() {
    __shared__ int warpTot[32];
    int t = threadIdx.x;
    const int CH = (NN + 1023) / 1024;   // 49
    int s = t * CH;
    int e = s + CH; if (e > NN) e = NN;
    int sum = 0;
    for (int i = s; i < e; i++) sum += g_counts[i];
    int lane = t & 31, wd = t >> 5;
    int v = sum;
#pragma unroll
    for (int o = 1; o < 32; o <<= 1) {
        int u = __shfl_up_sync(0xffffffffu, v, o);
        if (lane >= o) v += u;
    }
    if (lane == 31) warpTot[wd] = v;
    __syncthreads();
    if (wd == 0) {
        int w = warpTot[lane];
#pragma unroll
        for (int o = 1; o < 32; o <<= 1) {
            int u = __shfl_up_sync(0xffffffffu, w, o);
            if (lane >= o) w += u;
        }
        warpTot[lane] = w;
    }
    __syncthreads();
    int excl = (v - sum) + (wd > 0 ? warpTot[wd - 1] : 0);
    int run = excl;
    for (int i = s; i < e; i++) {
        g_rowptr[i] = run;
        g_cursor[i] = run;
        run += g_counts[i];
    }
    if (t == 1023) g_rowptr[NN] = run;
}
__global__ void k_scatter(const int* __restrict__ src, const int* __restrict__ dst,
                          const float* __restrict__ vals) {
    int e = blockIdx.x * blockDim.x + threadIdx.x;
    if (e < NE) {
        int d = dst[e];
        int p = atomicAdd(&g_cursor[d], 1);
        g_csr_src[p] = src[e];
        g_csr_val[p] = vals[e];
    }
}

// ---------------- converts ----------------
__global__ void k_conv_x(const float* __restrict__ X, __half* __restrict__ A) {
    long i = (long)blockIdx.x * blockDim.x + threadIdx.x;
    if (i >= (long)NN * KDIM / 4) return;
    float4 v = ((const float4*)X)[i];
    __half2 h01 = __floats2half2_rn(v.x, v.y);
    __half2 h23 = __floats2half2_rn(v.z, v.w);
    uint2 packed = make_uint2(*(uint32_t*)&h01, *(uint32_t*)&h23);
    ((uint2*)A)[i] = packed;
}

__global__ void k_conv_W(const float* __restrict__ W, __half* __restrict__ B, int N) {
    __shared__ float tile[32][33];
    int k0 = blockIdx.y * 32, n0 = blockIdx.x * 32;
    int tx = threadIdx.x, ty = threadIdx.y;   // 32 x 8
    for (int r = ty; r < 32; r += 8)
        tile[r][tx] = W[(size_t)(k0 + r) * N + n0 + tx];
    __syncthreads();
    for (int r = ty; r < 32; r += 8)
        B[(size_t)(n0 + r) * KDIM + k0 + tx] = __float2half_rn(tile[tx][r]);
}

// ---------------- fp16 mma.sync GEMM (row-offset variant) ----------------
__device__ __forceinline__ void ldsm_x4(uint32_t* r, uint32_t a) {
    asm volatile("ldmatrix.sync.aligned.m8n8.x4.shared.b16 {%0,%1,%2,%3}, [%4];"
                 : "=r"(r[0]), "=r"(r[1]), "=r"(r[2]), "=r"(r[3]) : "r"(a));
}
__device__ __forceinline__ void mma_f16(float* c, const uint32_t* a, uint32_t b0, uint32_t b1) {
    asm volatile(
        "mma.sync.aligned.m16n8k16.row.col.f32.f16.f16.f32 "
        "{%0,%1,%2,%3}, {%4,%5,%6,%7}, {%8,%9}, {%0,%1,%2,%3};"
        : "+f"(c[0]), "+f"(c[1]), "+f"(c[2]), "+f"(c[3])
        : "r"(a[0]), "r"(a[1]), "r"(a[2]), "r"(a[3]), "r"(b0), "r"(b1));
}
__device__ __forceinline__ void cpa16(uint32_t saddr, const void* g, uint32_t sz) {
    asm volatile("cp.async.cg.shared.global [%0], [%1], 16, %2;"
                 :: "r"(saddr), "l"(g), "r"(sz));
}

__global__ __launch_bounds__(512, 1)
void k_mma_gemm(const __half* __restrict__ A, const __half* __restrict__ B,
                const float* __restrict__ bias, __half* __restrict__ C,
                int m_off, int M, int N) {
    extern __shared__ __align__(1024) char smem[];
    const int A_SZ = 128 * 128;
    const int STG = A_SZ + 256 * 128;
    const int NCH = KDIM / 64;

    uint32_t sbase = smem_u32(smem);
    int tid = threadIdx.x;
    int w = tid >> 5, lane = tid & 31;
    int m0 = blockIdx.y * 128 + m_off, n0 = blockIdx.x * 256;
    int wm = (w >> 2) * 32, wn = (w & 3) * 64;

    auto load_stage = [&](int ch) {
        int s = ch & 3;
        int kk = ch * 64;
        uint32_t aS = sbase + s * STG;
        uint32_t bS = aS + A_SZ;
#pragma unroll
        for (int q = 0; q < 2; q++) {
            int u = tid + q * 512;
            int row = u >> 3, cb = u & 7;
            int gr = m0 + row;
            const __half* g = A + (size_t)gr * KDIM + kk + cb * 8;
            cpa16(aS + SWZ(row * 128 + cb * 16), g, (gr < M) ? 16u : 0u);
        }
#pragma unroll
        for (int q = 0; q < 4; q++) {
            int u = tid + q * 512;
            int row = u >> 3, cb = u & 7;
            const __half* g = B + (size_t)(n0 + row) * KDIM + kk + cb * 8;
            cpa16(bS + SWZ(row * 128 + cb * 16), g, 16u);
        }
        asm volatile("cp.async.commit_group;" ::: "memory");
    };

    float c[2][8][4];
#pragma unroll
    for (int mi = 0; mi < 2; mi++)
#pragma unroll
        for (int ni = 0; ni < 8; ni++)
#pragma unroll
            for (int j = 0; j < 4; j++) c[mi][ni][j] = 0.0f;

    load_stage(0);
    load_stage(1);
    load_stage(2);

    for (int ch = 0; ch < NCH; ch++) {
        int rem = NCH - 1 - ch;
        if (rem >= 2)
            asm volatile("cp.async.wait_group 2;" ::: "memory");
        else if (rem == 1)
            asm volatile("cp.async.wait_group 1;" ::: "memory");
        else
            asm volatile("cp.async.wait_group 0;" ::: "memory");
        __syncthreads();

        uint32_t aS = sbase + (ch & 3) * STG;
        uint32_t bS = aS + A_SZ;
        int lrow = lane & 15;
        int lcol = (lane >> 4) * 16;
#pragma unroll
        for (int ks = 0; ks < 4; ks++) {
            uint32_t a[2][4], bb[4][4];
#pragma unroll
            for (int mi = 0; mi < 2; mi++)
                ldsm_x4(a[mi], aS + SWZ((wm + mi * 16 + lrow) * 128 + ks * 32 + lcol));
#pragma unroll
            for (int p = 0; p < 4; p++)
                ldsm_x4(bb[p], bS + SWZ((wn + p * 16 + lrow) * 128 + ks * 32 + lcol));
#pragma unroll
            for (int mi = 0; mi < 2; mi++)
#pragma unroll
                for (int ni = 0; ni < 8; ni++)
                    mma_f16(c[mi][ni], a[mi],
                            bb[ni >> 1][(ni & 1)], bb[ni >> 1][(ni & 1) + 2]);
        }
        if (ch + 3 < NCH) load_stage(ch + 3);
    }

#pragma unroll
    for (int mi = 0; mi < 2; mi++) {
        int r0 = m0 + wm + mi * 16 + (lane >> 2);
        int r1 = r0 + 8;
#pragma unroll
        for (int ni = 0; ni < 8; ni++) {
            int col = n0 + wn + ni * 8 + (lane & 3) * 2;
            float b0 = bias[col], b1 = bias[col + 1];
            if (r0 < M) {
                __half2 v = __floats2half2_rn(c[mi][ni][0] + b0, c[mi][ni][1] + b1);
                *(__half2*)(C + (size_t)r0 * N + col) = v;
            }
            if (r1 < M) {
                __half2 v = __floats2half2_rn(c[mi][ni][2] + b0, c[mi][ni][3] + b1);
                *(__half2*)(C + (size_t)r1 * N + col) = v;
            }
        }
    }
}

// ---------------- SpMM 512-wide, row-offset variant ----------------
__global__ void k_spmm512(const __half* __restrict__ A, __half* __restrict__ OutH, int roff) {
    int row = blockIdx.x + roff;
    int t = threadIdx.x;               // 64
    int s = g_rowptr[row];
    int e = g_rowptr[row + 1];
    float acc[8];
#pragma unroll
    for (int j = 0; j < 8; j++) acc[j] = 0.f;
    for (int i = s; i < e; i++) {
        int sr = g_csr_src[i];
        float v = g_csr_val[i];
        uint4 raw = *(const uint4*)(A + (size_t)sr * 512 + t * 8);
        float2 f0 = __half22float2(*(__half2*)&raw.x);
        float2 f1 = __half22float2(*(__half2*)&raw.y);
        float2 f2 = __half22float2(*(__half2*)&raw.z);
        float2 f3 = __half22float2(*(__half2*)&raw.w);
        acc[0] = fmaf(v, f0.x, acc[0]); acc[1] = fmaf(v, f0.y, acc[1]);
        acc[2] = fmaf(v, f1.x, acc[2]); acc[3] = fmaf(v, f1.y, acc[3]);
        acc[4] = fmaf(v, f2.x, acc[4]); acc[5] = fmaf(v, f2.y, acc[5]);
        acc[6] = fmaf(v, f3.x, acc[6]); acc[7] = fmaf(v, f3.y, acc[7]);
    }
    __half2 h[4];
#pragma unroll
    for (int j = 0; j < 4; j++)
        h[j] = __floats2half2_rn(fmaxf(acc[j * 2], 0.f), fmaxf(acc[j * 2 + 1], 0.f));
    uint4 packed = make_uint4(*(uint32_t*)&h[0], *(uint32_t*)&h[1],
                              *(uint32_t*)&h[2], *(uint32_t*)&h[3]);
    *(uint4*)(OutH + (size_t)row * 512 + t * 8) = packed;
}

// ---------------- rank-k select + ssf sparsify ----------------
__global__ void k_thresh_ssf(const float* __restrict__ ssf, const float* __restrict__ sigma,
                             float* __restrict__ out_ssf, float* __restrict__ out_sigma) {
    __shared__ unsigned int hist[2048];
    __shared__ unsigned int s_prefix;
    __shared__ int s_rank;
    int t = threadIdx.x;  // 256
    if (t == 0) { s_prefix = 0u; s_rank = 8192; }
    __syncthreads();
    const int LO[3]  = {21, 10, 0};
    const int NB_[3] = {11, 11, 10};
    const int CHK[3] = {0, 21, 10};
    for (int p = 0; p < 3; p++) {
        for (int i = t; i < 2048; i += 256) hist[i] = 0u;
        __syncthreads();
        unsigned int pref = s_prefix;
        unsigned int mask = (1u << NB_[p]) - 1u;
        for (int i = t; i < NS * NC; i += 256) {
            unsigned int u = __float_as_uint(fabsf(ssf[i]));
            bool ok = (p == 0) ? true : ((u >> CHK[p]) == pref);
            if (ok) atomicAdd(&hist[(u >> LO[p]) & mask], 1u);
        }
        __syncthreads();
        if (t == 0) {
            int r = s_rank;
            unsigned int cum = 0;
            unsigned int nb = 1u << NB_[p];
            unsigned int b = 0;
            for (b = 0; b < nb; b++) {
                if (cum + hist[b] > (unsigned int)r) break;
                cum += hist[b];
            }
            s_rank = r - (int)cum;
            s_prefix = (s_prefix << NB_[p]) | b;
        }
        __syncthreads();
    }
    float thr = __uint_as_float(s_prefix);
    for (int i = t; i < NS * NC; i += 256) {
        float v = ssf[i];
        float o = (fabsf(v) >= thr) ? v : 0.0f;
        g_ssf_sp[i] = o;
        out_ssf[i] = o;
    }
    __syncthreads();
    if (t < NC) {
        float s = 0.f;
        for (int k = 0; k < NS; k++) {
            float v = g_ssf_sp[k * NC + t];
            s = fmaf(v, v, s);
        }
        g_colsq[t] = s;
        g_cn[t] = fmaxf(sqrtf(s), 1e-6f);
    }
    if (t == 0) out_sigma[0] = sigma[0];
}

// ---------------- fused: layer-3 spmm + out + spatial loss ----------------
__device__ __forceinline__ float warp_max(float v) {
#pragma unroll
    for (int o = 16; o > 0; o >>= 1) v = fmaxf(v, __shfl_xor_sync(0xffffffffu, v, o));
    return v;
}
__device__ __forceinline__ float warp_sum(float v) {
#pragma unroll
    for (int o = 16; o > 0; o >>= 1) v += __shfl_xor_sync(0xffffffffu, v, o);
    return v;
}

__global__ __launch_bounds__(64)
void k_spmm_loss(const __half* __restrict__ A, float* __restrict__ h_out,
                 float* __restrict__ out, float* __restrict__ loss) {
    __shared__ float sh[NS];
    __shared__ float redh[2], redm[2], redms[2], reds[2], redss[2];
    int row = blockIdx.x;
    int t = threadIdx.x;          // 64
    int lane = t & 31, wd = t >> 5;
    int s = g_rowptr[row];
    int e = g_rowptr[row + 1];
    float4 acc = make_float4(0.f, 0.f, 0.f, 0.f);
    for (int i = s; i < e; i++) {
        int sr = g_csr_src[i];
        float v = g_csr_val[i];
        uint2 raw = *(const uint2*)(A + (size_t)sr * NS + t * 4);
        float2 f01 = __half22float2(*(__half2*)&raw.x);
        float2 f23 = __half22float2(*(__half2*)&raw.y);
        acc.x = fmaf(v, f01.x, acc.x);
        acc.y = fmaf(v, f01.y, acc.y);
        acc.z = fmaf(v, f23.x, acc.z);
        acc.w = fmaf(v, f23.y, acc.w);
    }
    *(float4*)(h_out + (size_t)row * NS + t * 4) = acc;
    *(float4*)(sh + t * 4) = acc;
    float ssq = acc.x * acc.x + acc.y * acc.y + acc.z * acc.z + acc.w * acc.w;
    float hw = warp_sum(ssq);
    if (lane == 0) redh[wd] = hw;
    __syncthreads();
    float hh = redh[0] + redh[1];

    float dot = 0.f;
#pragma unroll 4
    for (int k = 0; k < NS; k++)
        dot = fmaf(sh[k], g_ssf_sp[k * NC + t], dot);

    float sq = hh - 2.0f * dot + g_colsq[t];
    float dist = -sqrtf(fmaxf(sq, 1e-12f));
    float hn = fmaxf(sqrtf(hh), 1e-6f);
    float sim = dot / (hn * g_cn[t]);

    float mdw = warp_max(dist);
    float msw = warp_max(sim);
    if (lane == 0) { redm[wd] = mdw; redms[wd] = msw; }
    __syncthreads();
    float md = fmaxf(redm[0], redm[1]);
    float ms = fmaxf(redms[0], redms[1]);
    float sdw = warp_sum(expf(dist - md));
    float ssw = warp_sum(expf(sim - ms));
    if (lane == 0) { reds[wd] = sdw; redss[wd] = ssw; }
    __syncthreads();
    float sd = reds[0] + reds[1];
    float ss = redss[0] + redss[1];

    float lsd = dist - md - logf(sd);
    float lss = sim - ms - logf(ss);
    out[(size_t)row * NC + t]  = dot;
    loss[(size_t)row * NC + t] = 0.5f * (lsd + lss);
}

// ---------------- launch ----------------
extern "C" void kernel_launch(void* const* d_in, const int* in_sizes, int n_in,
                              void* d_out, int out_size) {
    const float* x    = (const float*)d_in[0];
    const int*   src  = (const int*)d_in[1];
    const int*   dst  = (const int*)d_in[2];
    const float* vals = (const float*)d_in[3];
    const float* W1   = (const float*)d_in[4];
    const float* b1   = (const float*)d_in[5];
    const float* W2   = (const float*)d_in[6];
    const float* b2   = (const float*)d_in[7];
    const float* W3   = (const float*)d_in[8];
    const float* b3   = (const float*)d_in[9];
    const float* ssf  = (const float*)d_in[10];
    const float* sig  = (const float*)d_in[11];
    float* out = (float*)d_out;

    size_t o_out = 0;
    size_t o_ssf = (size_t)NN * NC;
    size_t o_h   = o_ssf + (size_t)NS * NC;
    size_t o_loss = o_h + (size_t)NN * NS;
    size_t o_sigma = o_loss + (size_t)NN * NC;

    __half *bufC = nullptr, *bufD = nullptr;
    __half *A = nullptr, *B1 = nullptr, *B2 = nullptr, *B3 = nullptr;
    cudaGetSymbolAddress((void**)&bufC, g_bufC);
    cudaGetSymbolAddress((void**)&bufD, g_bufD);
    cudaGetSymbolAddress((void**)&A, g_A);
    cudaGetSymbolAddress((void**)&B1, g_B1);
    cudaGetSymbolAddress((void**)&B2, g_B2);
    cudaGetSymbolAddress((void**)&B3, g_B3);

    const int SMEM_MMA = 4 * (128 + 256) * 128;   // 196608
    cudaFuncSetAttribute(k_mma_gemm, cudaFuncAttributeMaxDynamicSharedMemorySize, SMEM_MMA);

    dim3 wblk(32, 8);
    dim3 wgrid12(NH / 32, KDIM / 32);
    dim3 wgrid3(NS / 32, KDIM / 32);
    const int NLO = SPLIT / 128;                    // 195 row-tiles, rows [0, 24960)
    const int NHI = (NN - SPLIT + 127) / 128;       // 196 row-tiles, rows [24960, 50000)
    dim3 g12full(NH / 256, (NN + 127) / 128);
    dim3 g12lo(NH / 256, NLO), g12hi(NH / 256, NHI);
    dim3 g3lo(NS / 256, NLO), g3hi(NS / 256, NHI);

    bool fork = g_res.ok;
    cudaStream_t s2 = fork ? g_res.s2 : (cudaStream_t)0;

    if (fork) {
        cudaEventRecord(g_res.eFork, 0);
        cudaStreamWaitEvent(s2, g_res.eFork, 0);
    }

    // ---- side: W1 convert, CSR build, W2/W3 converts, thresh ----
    k_conv_W<<<wgrid12, wblk, 0, s2>>>(W1, B1, NH);
    if (fork) cudaEventRecord(g_res.eW1, s2);
    k_zero_counts<<<(NN + 255) / 256, 256, 0, s2>>>();
    k_count<<<(NE + 255) / 256, 256, 0, s2>>>(dst);
    k_scan<<<1, 1024, 0, s2>>>();
    k_scatter<<<(NE + 255) / 256, 256, 0, s2>>>(src, dst, vals);
    if (fork) cudaEventRecord(g_res.eCSR, s2);
    k_conv_W<<<wgrid12, wblk, 0, s2>>>(W2, B2, NH);
    k_conv_W<<<wgrid3, wblk, 0, s2>>>(W3, B3, NS);
    if (fork) cudaEventRecord(g_res.eW23, s2);
    k_thresh_ssf<<<1, 256, 0, s2>>>(ssf, sig, out + o_ssf, out + o_sigma);
    if (fork) cudaEventRecord(g_res.eSSF, s2);

    // ---- main: conv_x, GEMM1(full -> bufC) ----
    k_conv_x<<<(int)(((long)NN * KDIM / 4 + 255) / 256), 256>>>(x, A);
    if (fork) cudaStreamWaitEvent(0, g_res.eW1, 0);
    k_mma_gemm<<<g12full, 512, SMEM_MMA>>>(A, B1, b1, bufC, 0, NN, NH);

    // ---- layer 1->2 boundary, pipelined halves ----
    if (fork) cudaStreamWaitEvent(0, g_res.eCSR, 0);
    k_spmm512<<<SPLIT, 64>>>(bufC, A, 0);                      // spmm1_lo (main)
    if (fork) cudaEventRecord(g_res.eS1lo, 0);
    if (fork) cudaStreamWaitEvent(0, g_res.eW23, 0);
    k_mma_gemm<<<g12lo, 512, SMEM_MMA>>>(A, B2, b2, bufD, 0, SPLIT, NH);   // GEMM2_lo (main)

    if (fork) cudaStreamWaitEvent(s2, g_res.eS1lo, 0);
    k_spmm512<<<NN - SPLIT, 64, 0, s2>>>(bufC, A, SPLIT);      // spmm1_hi (side)
    k_mma_gemm<<<g12hi, 512, SMEM_MMA, s2>>>(A, B2, b2, bufD, SPLIT, NN, NH);  // GEMM2_hi (side)
    if (fork) cudaEventRecord(g_res.eG2hi, s2);

    // ---- layer 2->3 boundary, pipelined halves ----
    if (fork) cudaStreamWaitEvent(0, g_res.eG2hi, 0);
    k_spmm512<<<SPLIT, 64>>>(bufD, A, 0);                      // spmm2_lo (main)
    if (fork) cudaEventRecord(g_res.eS2lo, 0);
    k_mma_gemm<<<g3lo, 512, SMEM_MMA>>>(A, B3, b3, bufC, 0, SPLIT, NS);    // GEMM3_lo (main)

    if (fork) cudaStreamWaitEvent(s2, g_res.eS2lo, 0);
    k_spmm512<<<NN - SPLIT, 64, 0, s2>>>(bufD, A, SPLIT);      // spmm2_hi (side)
    k_mma_gemm<<<g3hi, 512, SMEM_MMA, s2>>>(A, B3, b3, bufC, SPLIT, NN, NS);   // GEMM3_hi (side)
    if (fork) cudaEventRecord(g_res.eG3hi, s2);

    // ---- final: fused spmm + out + loss (needs full GEMM3 + ssf) ----
    if (fork) {
        cudaStreamWaitEvent(0, g_res.eG3hi, 0);
        cudaStreamWaitEvent(0, g_res.eSSF, 0);
    }
    k_spmm_loss<<<NN, 64>>>(bufC, out + o_h, out + o_out, out + o_loss);
}

// round 13
// speedup vs baseline: 1.1949x; 1.1949x over previous
#include <cuda_runtime.h>
#include <cuda_bf16.h>
#include <cuda_fp16.h>
#include <math.h>
#include <stdint.h>

#define NN 50000
#define NF 512
#define NH 512
#define NS 256
#define NC 64
#define NE 1600000
#define KDIM 512
#define NBLK 196           // ceil(NN / 256)

// ---------------- scratch ----------------
static __device__ __half g_bufC[(size_t)NN * NH];   // GEMM out / spmm gather in
static __device__ __half g_A[(size_t)NN * KDIM];    // activations fp16
static __device__ __half g_B1[NH * KDIM];
static __device__ __half g_B2[NH * KDIM];
static __device__ __half g_B3[NS * KDIM];
static __device__ int   g_counts[NN];
static __device__ int   g_blockSum[NBLK];
static __device__ int   g_blockOff[NBLK];
static __device__ int   g_rowptr[NN + 1];
static __device__ int   g_cursor[NN];
static __device__ int   g_csr_src[NE];
static __device__ float g_csr_val[NE];
static __device__ float g_ssf_sp[NS * NC];
static __device__ float g_colsq[NC];
static __device__ float g_cn[NC];

#define SWZ(o) ((o) ^ (((o) >> 3) & 0x70))

__device__ __forceinline__ uint32_t smem_u32(const void* p) {
    uint32_t a;
    asm("{ .reg .u64 t; cvta.to.shared.u64 t, %1; cvt.u32.u64 %0, t; }" : "=r"(a) : "l"(p));
    return a;
}

// ---------------- stream/event resources ----------------
struct SideRes {
    cudaStream_t s2 = nullptr;
    cudaEvent_t eFork = nullptr, eW1 = nullptr, eCSR = nullptr, eW23 = nullptr, eSSF = nullptr;
    bool ok = false;
    SideRes() {
        bool o = cudaStreamCreateWithFlags(&s2, cudaStreamNonBlocking) == cudaSuccess;
        cudaEvent_t* evs[5] = {&eFork, &eW1, &eCSR, &eW23, &eSSF};
        for (int i = 0; i < 5 && o; i++)
            o = cudaEventCreateWithFlags(evs[i], cudaEventDisableTiming) == cudaSuccess;
        ok = o;
    }
};
static SideRes g_res;

// ---------------- CSR build ----------------
__global__ void k_zero_counts() {
    int i = blockIdx.x * blockDim.x + threadIdx.x;
    if (i < NN) g_counts[i] = 0;
}
__global__ void k_count(const int* __restrict__ dst) {
    int e = blockIdx.x * blockDim.x + threadIdx.x;
    if (e < NE) atomicAdd(&g_counts[dst[e]], 1);
}

// 3-kernel wide scan: per-block sums -> tiny combine -> apply offsets
__global__ void k_scan1() {
    __shared__ int warpTot[8];
    int b = blockIdx.x, t = threadIdx.x;
    int i = b * 256 + t;
    int c = (i < NN) ? g_counts[i] : 0;
    int lane = t & 31, wd = t >> 5;
    int v = c;
#pragma unroll
    for (int o = 16; o > 0; o >>= 1) v += __shfl_xor_sync(0xffffffffu, v, o);
    if (lane == 0) warpTot[wd] = v;
    __syncthreads();
    if (t == 0) {
        int s = 0;
#pragma unroll
        for (int j = 0; j < 8; j++) s += warpTot[j];
        g_blockSum[b] = s;
    }
}
__global__ void k_scan2() {
    __shared__ int warpTot[8];
    int t = threadIdx.x;   // 256
    int v = (t < NBLK) ? g_blockSum[t] : 0;
    int lane = t & 31, wd = t >> 5;
    int inc = v;
#pragma unroll
    for (int o = 1; o < 32; o <<= 1) {
        int u = __shfl_up_sync(0xffffffffu, inc, o);
        if (lane >= o) inc += u;
    }
    if (lane == 31) warpTot[wd] = inc;
    __syncthreads();
    if (t == 0) {
        int r = 0;
#pragma unroll
        for (int j = 0; j < 8; j++) { int x = warpTot[j]; warpTot[j] = r; r += x; }
        g_rowptr[NN] = r;
    }
    __syncthreads();
    int excl = inc - v + warpTot[wd];
    if (t < NBLK) g_blockOff[t] = excl;
}
__global__ void k_scan3() {
    __shared__ int warpTot[8];
    int b = blockIdx.x, t = threadIdx.x;
    int i = b * 256 + t;
    int c = (i < NN) ? g_counts[i] : 0;
    int lane = t & 31, wd = t >> 5;
    int inc = c;
#pragma unroll
    for (int o = 1; o < 32; o <<= 1) {
        int u = __shfl_up_sync(0xffffffffu, inc, o);
        if (lane >= o) inc += u;
    }
    if (lane == 31) warpTot[wd] = inc;
    __syncthreads();
    if (t == 0) {
        int r = 0;
#pragma unroll
        for (int j = 0; j < 8; j++) { int x = warpTot[j]; warpTot[j] = r; r += x; }
    }
    __syncthreads();
    int excl = inc - c + warpTot[wd] + g_blockOff[b];
    if (i < NN) {
        g_rowptr[i] = excl;
        g_cursor[i] = excl;
    }
}
__global__ void k_scatter(const int* __restrict__ src, const int* __restrict__ dst,
                          const float* __restrict__ vals) {
    int e = blockIdx.x * blockDim.x + threadIdx.x;
    if (e < NE) {
        int d = dst[e];
        int p = atomicAdd(&g_cursor[d], 1);
        g_csr_src[p] = src[e];
        g_csr_val[p] = vals[e];
    }
}

// ---------------- converts ----------------
__global__ void k_conv_x(const float* __restrict__ X, __half* __restrict__ A) {
    long i = (long)blockIdx.x * blockDim.x + threadIdx.x;
    if (i >= (long)NN * KDIM / 4) return;
    float4 v = ((const float4*)X)[i];
    __half2 h01 = __floats2half2_rn(v.x, v.y);
    __half2 h23 = __floats2half2_rn(v.z, v.w);
    uint2 packed = make_uint2(*(uint32_t*)&h01, *(uint32_t*)&h23);
    ((uint2*)A)[i] = packed;
}

__global__ void k_conv_W(const float* __restrict__ W, __half* __restrict__ B, int N) {
    __shared__ float tile[32][33];
    int k0 = blockIdx.y * 32, n0 = blockIdx.x * 32;
    int tx = threadIdx.x, ty = threadIdx.y;   // 32 x 8
    for (int r = ty; r < 32; r += 8)
        tile[r][tx] = W[(size_t)(k0 + r) * N + n0 + tx];
    __syncthreads();
    for (int r = ty; r < 32; r += 8)
        B[(size_t)(n0 + r) * KDIM + k0 + tx] = __float2half_rn(tile[tx][r]);
}

// ---------------- fp16 mma.sync GEMM ----------------
__device__ __forceinline__ void ldsm_x4(uint32_t* r, uint32_t a) {
    asm volatile("ldmatrix.sync.aligned.m8n8.x4.shared.b16 {%0,%1,%2,%3}, [%4];"
                 : "=r"(r[0]), "=r"(r[1]), "=r"(r[2]), "=r"(r[3]) : "r"(a));
}
__device__ __forceinline__ void mma_f16(float* c, const uint32_t* a, uint32_t b0, uint32_t b1) {
    asm volatile(
        "mma.sync.aligned.m16n8k16.row.col.f32.f16.f16.f32 "
        "{%0,%1,%2,%3}, {%4,%5,%6,%7}, {%8,%9}, {%0,%1,%2,%3};"
        : "+f"(c[0]), "+f"(c[1]), "+f"(c[2]), "+f"(c[3])
        : "r"(a[0]), "r"(a[1]), "r"(a[2]), "r"(a[3]), "r"(b0), "r"(b1));
}
__device__ __forceinline__ void cpa16(uint32_t saddr, const void* g, uint32_t sz) {
    asm volatile("cp.async.cg.shared.global [%0], [%1], 16, %2;"
                 :: "r"(saddr), "l"(g), "r"(sz));
}

__global__ __launch_bounds__(512, 1)
void k_mma_gemm(const __half* __restrict__ A, const __half* __restrict__ B,
                const float* __restrict__ bias, __half* __restrict__ C, int M, int N) {
    extern __shared__ __align__(1024) char smem[];
    const int A_SZ = 128 * 128;
    const int STG = A_SZ + 256 * 128;
    const int NCH = KDIM / 64;

    uint32_t sbase = smem_u32(smem);
    int tid = threadIdx.x;
    int w = tid >> 5, lane = tid & 31;
    int m0 = blockIdx.y * 128, n0 = blockIdx.x * 256;
    int wm = (w >> 2) * 32, wn = (w & 3) * 64;

    auto load_stage = [&](int ch) {
        int s = ch & 3;
        int kk = ch * 64;
        uint32_t aS = sbase + s * STG;
        uint32_t bS = aS + A_SZ;
#pragma unroll
        for (int q = 0; q < 2; q++) {
            int u = tid + q * 512;
            int row = u >> 3, cb = u & 7;
            int gr = m0 + row;
            const __half* g = A + (size_t)gr * KDIM + kk + cb * 8;
            cpa16(aS + SWZ(row * 128 + cb * 16), g, (gr < M) ? 16u : 0u);
        }
#pragma unroll
        for (int q = 0; q < 4; q++) {
            int u = tid + q * 512;
            int row = u >> 3, cb = u & 7;
            const __half* g = B + (size_t)(n0 + row) * KDIM + kk + cb * 8;
            cpa16(bS + SWZ(row * 128 + cb * 16), g, 16u);
        }
        asm volatile("cp.async.commit_group;" ::: "memory");
    };

    float c[2][8][4];
#pragma unroll
    for (int mi = 0; mi < 2; mi++)
#pragma unroll
        for (int ni = 0; ni < 8; ni++)
#pragma unroll
            for (int j = 0; j < 4; j++) c[mi][ni][j] = 0.0f;

    load_stage(0);
    load_stage(1);
    load_stage(2);

    for (int ch = 0; ch < NCH; ch++) {
        int rem = NCH - 1 - ch;
        if (rem >= 2)
            asm volatile("cp.async.wait_group 2;" ::: "memory");
        else if (rem == 1)
            asm volatile("cp.async.wait_group 1;" ::: "memory");
        else
            asm volatile("cp.async.wait_group 0;" ::: "memory");
        __syncthreads();

        uint32_t aS = sbase + (ch & 3) * STG;
        uint32_t bS = aS + A_SZ;
        int lrow = lane & 15;
        int lcol = (lane >> 4) * 16;
#pragma unroll
        for (int ks = 0; ks < 4; ks++) {
            uint32_t a[2][4], bb[4][4];
#pragma unroll
            for (int mi = 0; mi < 2; mi++)
                ldsm_x4(a[mi], aS + SWZ((wm + mi * 16 + lrow) * 128 + ks * 32 + lcol));
#pragma unroll
            for (int p = 0; p < 4; p++)
                ldsm_x4(bb[p], bS + SWZ((wn + p * 16 + lrow) * 128 + ks * 32 + lcol));
#pragma unroll
            for (int mi = 0; mi < 2; mi++)
#pragma unroll
                for (int ni = 0; ni < 8; ni++)
                    mma_f16(c[mi][ni], a[mi],
                            bb[ni >> 1][(ni & 1)], bb[ni >> 1][(ni & 1) + 2]);
        }
        if (ch + 3 < NCH) load_stage(ch + 3);
    }

#pragma unroll
    for (int mi = 0; mi < 2; mi++) {
        int r0 = m0 + wm + mi * 16 + (lane >> 2);
        int r1 = r0 + 8;
#pragma unroll
        for (int ni = 0; ni < 8; ni++) {
            int col = n0 + wn + ni * 8 + (lane & 3) * 2;
            float b0 = bias[col], b1 = bias[col + 1];
            if (r0 < M) {
                __half2 v = __floats2half2_rn(c[mi][ni][0] + b0, c[mi][ni][1] + b1);
                *(__half2*)(C + (size_t)r0 * N + col) = v;
            }
            if (r1 < M) {
                __half2 v = __floats2half2_rn(c[mi][ni][2] + b0, c[mi][ni][3] + b1);
                *(__half2*)(C + (size_t)r1 * N + col) = v;
            }
        }
    }
}

// ---------------- SpMM 512-wide ----------------
__global__ void k_spmm512(const __half* __restrict__ A, __half* __restrict__ OutH) {
    int row = blockIdx.x;
    int t = threadIdx.x;               // 64
    int s = g_rowptr[row];
    int e = g_rowptr[row + 1];
    float acc[8];
#pragma unroll
    for (int j = 0; j < 8; j++) acc[j] = 0.f;
    for (int i = s; i < e; i++) {
        int sr = g_csr_src[i];
        float v = g_csr_val[i];
        uint4 raw = *(const uint4*)(A + (size_t)sr * 512 + t * 8);
        float2 f0 = __half22float2(*(__half2*)&raw.x);
        float2 f1 = __half22float2(*(__half2*)&raw.y);
        float2 f2 = __half22float2(*(__half2*)&raw.z);
        float2 f3 = __half22float2(*(__half2*)&raw.w);
        acc[0] = fmaf(v, f0.x, acc[0]); acc[1] = fmaf(v, f0.y, acc[1]);
        acc[2] = fmaf(v, f1.x, acc[2]); acc[3] = fmaf(v, f1.y, acc[3]);
        acc[4] = fmaf(v, f2.x, acc[4]); acc[5] = fmaf(v, f2.y, acc[5]);
        acc[6] = fmaf(v, f3.x, acc[6]); acc[7] = fmaf(v, f3.y, acc[7]);
    }
    __half2 h[4];
#pragma unroll
    for (int j = 0; j < 4; j++)
        h[j] = __floats2half2_rn(fmaxf(acc[j * 2], 0.f), fmaxf(acc[j * 2 + 1], 0.f));
    uint4 packed = make_uint4(*(uint32_t*)&h[0], *(uint32_t*)&h[1],
                              *(uint32_t*)&h[2], *(uint32_t*)&h[3]);
    *(uint4*)(OutH + (size_t)row * 512 + t * 8) = packed;
}

// ---------------- rank-k select + ssf sparsify ----------------
__global__ void k_thresh_ssf(const float* __restrict__ ssf, const float* __restrict__ sigma,
                             float* __restrict__ out_ssf, float* __restrict__ out_sigma) {
    __shared__ unsigned int hist[2048];
    __shared__ unsigned int s_prefix;
    __shared__ int s_rank;
    int t = threadIdx.x;  // 256
    if (t == 0) { s_prefix = 0u; s_rank = 8192; }
    __syncthreads();
    const int LO[3]  = {21, 10, 0};
    const int NB_[3] = {11, 11, 10};
    const int CHK[3] = {0, 21, 10};
    for (int p = 0; p < 3; p++) {
        for (int i = t; i < 2048; i += 256) hist[i] = 0u;
        __syncthreads();
        unsigned int pref = s_prefix;
        unsigned int mask = (1u << NB_[p]) - 1u;
        for (int i = t; i < NS * NC; i += 256) {
            unsigned int u = __float_as_uint(fabsf(ssf[i]));
            bool ok = (p == 0) ? true : ((u >> CHK[p]) == pref);
            if (ok) atomicAdd(&hist[(u >> LO[p]) & mask], 1u);
        }
        __syncthreads();
        if (t == 0) {
            int r = s_rank;
            unsigned int cum = 0;
            unsigned int nb = 1u << NB_[p];
            unsigned int b = 0;
            for (b = 0; b < nb; b++) {
                if (cum + hist[b] > (unsigned int)r) break;
                cum += hist[b];
            }
            s_rank = r - (int)cum;
            s_prefix = (s_prefix << NB_[p]) | b;
        }
        __syncthreads();
    }
    float thr = __uint_as_float(s_prefix);
    for (int i = t; i < NS * NC; i += 256) {
        float v = ssf[i];
        float o = (fabsf(v) >= thr) ? v : 0.0f;
        g_ssf_sp[i] = o;
        out_ssf[i] = o;
    }
    __syncthreads();
    if (t < NC) {
        float s = 0.f;
        for (int k = 0; k < NS; k++) {
            float v = g_ssf_sp[k * NC + t];
            s = fmaf(v, v, s);
        }
        g_colsq[t] = s;
        g_cn[t] = fmaxf(sqrtf(s), 1e-6f);
    }
    if (t == 0) out_sigma[0] = sigma[0];
}

// ---------------- fused: layer-3 spmm + out + spatial loss ----------------
__device__ __forceinline__ float warp_max(float v) {
#pragma unroll
    for (int o = 16; o > 0; o >>= 1) v = fmaxf(v, __shfl_xor_sync(0xffffffffu, v, o));
    return v;
}
__device__ __forceinline__ float warp_sum(float v) {
#pragma unroll
    for (int o = 16; o > 0; o >>= 1) v += __shfl_xor_sync(0xffffffffu, v, o);
    return v;
}

__global__ __launch_bounds__(64)
void k_spmm_loss(const __half* __restrict__ A, float* __restrict__ h_out,
                 float* __restrict__ out, float* __restrict__ loss) {
    __shared__ float sh[NS];
    __shared__ float redh[2], redm[2], redms[2], reds[2], redss[2];
    int row = blockIdx.x;
    int t = threadIdx.x;          // 64
    int lane = t & 31, wd = t >> 5;
    int s = g_rowptr[row];
    int e = g_rowptr[row + 1];
    float4 acc = make_float4(0.f, 0.f, 0.f, 0.f);
    for (int i = s; i < e; i++) {
        int sr = g_csr_src[i];
        float v = g_csr_val[i];
        uint2 raw = *(const uint2*)(A + (size_t)sr * NS + t * 4);
        float2 f01 = __half22float2(*(__half2*)&raw.x);
        float2 f23 = __half22float2(*(__half2*)&raw.y);
        acc.x = fmaf(v, f01.x, acc.x);
        acc.y = fmaf(v, f01.y, acc.y);
        acc.z = fmaf(v, f23.x, acc.z);
        acc.w = fmaf(v, f23.y, acc.w);
    }
    *(float4*)(h_out + (size_t)row * NS + t * 4) = acc;
    *(float4*)(sh + t * 4) = acc;
    float ssq = acc.x * acc.x + acc.y * acc.y + acc.z * acc.z + acc.w * acc.w;
    float hw = warp_sum(ssq);
    if (lane == 0) redh[wd] = hw;
    __syncthreads();
    float hh = redh[0] + redh[1];

    float dot = 0.f;
#pragma unroll 4
    for (int k = 0; k < NS; k++)
        dot = fmaf(sh[k], g_ssf_sp[k * NC + t], dot);

    float sq = hh - 2.0f * dot + g_colsq[t];
    float dist = -sqrtf(fmaxf(sq, 1e-12f));
    float hn = fmaxf(sqrtf(hh), 1e-6f);
    float sim = dot / (hn * g_cn[t]);

    float mdw = warp_max(dist);
    float msw = warp_max(sim);
    if (lane == 0) { redm[wd] = mdw; redms[wd] = msw; }
    __syncthreads();
    float md = fmaxf(redm[0], redm[1]);
    float ms = fmaxf(redms[0], redms[1]);
    float sdw = warp_sum(expf(dist - md));
    float ssw = warp_sum(expf(sim - ms));
    if (lane == 0) { reds[wd] = sdw; redss[wd] = ssw; }
    __syncthreads();
    float sd = reds[0] + reds[1];
    float ss = redss[0] + redss[1];

    float lsd = dist - md - logf(sd);
    float lss = sim - ms - logf(ss);
    out[(size_t)row * NC + t]  = dot;
    loss[(size_t)row * NC + t] = 0.5f * (lsd + lss);
}

// ---------------- launch ----------------
extern "C" void kernel_launch(void* const* d_in, const int* in_sizes, int n_in,
                              void* d_out, int out_size) {
    const float* x    = (const float*)d_in[0];
    const int*   src  = (const int*)d_in[1];
    const int*   dst  = (const int*)d_in[2];
    const float* vals = (const float*)d_in[3];
    const float* W1   = (const float*)d_in[4];
    const float* b1   = (const float*)d_in[5];
    const float* W2   = (const float*)d_in[6];
    const float* b2   = (const float*)d_in[7];
    const float* W3   = (const float*)d_in[8];
    const float* b3   = (const float*)d_in[9];
    const float* ssf  = (const float*)d_in[10];
    const float* sig  = (const float*)d_in[11];
    float* out = (float*)d_out;

    size_t o_out = 0;
    size_t o_ssf = (size_t)NN * NC;
    size_t o_h   = o_ssf + (size_t)NS * NC;
    size_t o_loss = o_h + (size_t)NN * NS;
    size_t o_sigma = o_loss + (size_t)NN * NC;

    __half* bufC = nullptr;
    __half *A = nullptr, *B1 = nullptr, *B2 = nullptr, *B3 = nullptr;
    cudaGetSymbolAddress((void**)&bufC, g_bufC);
    cudaGetSymbolAddress((void**)&A, g_A);
    cudaGetSymbolAddress((void**)&B1, g_B1);
    cudaGetSymbolAddress((void**)&B2, g_B2);
    cudaGetSymbolAddress((void**)&B3, g_B3);

    const int SMEM_MMA = 4 * (128 + 256) * 128;   // 196608
    cudaFuncSetAttribute(k_mma_gemm, cudaFuncAttributeMaxDynamicSharedMemorySize, SMEM_MMA);

    dim3 wblk(32, 8);
    dim3 wgrid12(NH / 32, KDIM / 32);
    dim3 wgrid3(NS / 32, KDIM / 32);
    dim3 g12(NH / 256, (NN + 127) / 128);   // (2, 391)
    dim3 g3(NS / 256, (NN + 127) / 128);    // (1, 391)

    bool fork = g_res.ok;
    cudaStream_t s2 = fork ? g_res.s2 : (cudaStream_t)0;

    if (fork) {
        cudaEventRecord(g_res.eFork, 0);
        cudaStreamWaitEvent(s2, g_res.eFork, 0);
    }

    // ---- side stream: W1 convert, CSR build (wide scan), W2/W3, thresh ----
    k_conv_W<<<wgrid12, wblk, 0, s2>>>(W1, B1, NH);
    if (fork) cudaEventRecord(g_res.eW1, s2);
    k_zero_counts<<<(NN + 255) / 256, 256, 0, s2>>>();
    k_count<<<(NE + 255) / 256, 256, 0, s2>>>(dst);
    k_scan1<<<NBLK, 256, 0, s2>>>();
    k_scan2<<<1, 256, 0, s2>>>();
    k_scan3<<<NBLK, 256, 0, s2>>>();
    k_scatter<<<(NE + 255) / 256, 256, 0, s2>>>(src, dst, vals);
    if (fork) cudaEventRecord(g_res.eCSR, s2);
    k_conv_W<<<wgrid12, wblk, 0, s2>>>(W2, B2, NH);
    k_conv_W<<<wgrid3, wblk, 0, s2>>>(W3, B3, NS);
    if (fork) cudaEventRecord(g_res.eW23, s2);
    k_thresh_ssf<<<1, 256, 0, s2>>>(ssf, sig, out + o_ssf, out + o_sigma);
    if (fork) cudaEventRecord(g_res.eSSF, s2);

    // ---- main stream ----
    k_conv_x<<<(int)(((long)NN * KDIM / 4 + 255) / 256), 256>>>(x, A);
    if (fork) cudaStreamWaitEvent(0, g_res.eW1, 0);
    k_mma_gemm<<<g12, 512, SMEM_MMA>>>(A, B1, b1, bufC, NN, NH);
    if (fork) cudaStreamWaitEvent(0, g_res.eCSR, 0);
    k_spmm512<<<NN, 64>>>(bufC, A);

    if (fork) cudaStreamWaitEvent(0, g_res.eW23, 0);
    k_mma_gemm<<<g12, 512, SMEM_MMA>>>(A, B2, b2, bufC, NN, NH);
    k_spmm512<<<NN, 64>>>(bufC, A);

    k_mma_gemm<<<g3, 512, SMEM_MMA>>>(A, B3, b3, bufC, NN, NS);
    if (fork) cudaStreamWaitEvent(0, g_res.eSSF, 0);
    k_spmm_loss<<<NN, 64>>>(bufC, out + o_h, out + o_out, out + o_loss);
}

// round 16
// speedup vs baseline: 1.2627x; 1.0568x over previous
#include <cuda_runtime.h>
#include <cuda_bf16.h>
#include <cuda_fp16.h>
#include <math.h>
#include <stdint.h>

#define NN 50000
#define NF 512
#define NH 512
#define NS 256
#define NC 64
#define NE 1600000
#define KDIM 512
#define NBLK 196           // ceil(NN / 256)

// ---------------- scratch ----------------
static __device__ __half g_bufC[(size_t)NN * NH];   // GEMM out / spmm gather in
static __device__ __half g_A[(size_t)NN * KDIM];    // activations fp16
static __device__ __half g_B1[NH * KDIM];
static __device__ __half g_B2[NH * KDIM];
static __device__ __half g_B3[NS * KDIM];
static __device__ int   g_counts[NN];
static __device__ int   g_blockSum[NBLK];
static __device__ int   g_blockOff[NBLK];
static __device__ int   g_rowptr[NN + 1];
static __device__ int   g_cursor[NN];
static __device__ int   g_csr_src[NE];
static __device__ float g_csr_val[NE];
static __device__ float g_ssf_sp[NS * NC];
static __device__ float g_colsq[NC];
static __device__ float g_cn[NC];

#define SWZ(o) ((o) ^ (((o) >> 3) & 0x70))

__device__ __forceinline__ uint32_t smem_u32(const void* p) {
    uint32_t a;
    asm("{ .reg .u64 t; cvta.to.shared.u64 t, %1; cvt.u32.u64 %0, t; }" : "=r"(a) : "l"(p));
    return a;
}

// ---------------- stream/event resources ----------------
struct SideRes {
    cudaStream_t s2 = nullptr;
    cudaEvent_t eFork = nullptr, eW1 = nullptr, eCSR = nullptr, eW23 = nullptr, eSSF = nullptr;
    bool ok = false;
    SideRes() {
        bool o = cudaStreamCreateWithFlags(&s2, cudaStreamNonBlocking) == cudaSuccess;
        cudaEvent_t* evs[5] = {&eFork, &eW1, &eCSR, &eW23, &eSSF};
        for (int i = 0; i < 5 && o; i++)
            o = cudaEventCreateWithFlags(evs[i], cudaEventDisableTiming) == cudaSuccess;
        ok = o;
    }
};
static SideRes g_res;

// ---------------- CSR build ----------------
__global__ void k_zero_counts() {
    int i = blockIdx.x * blockDim.x + threadIdx.x;
    if (i < NN) g_counts[i] = 0;
}
__global__ void k_count(const int* __restrict__ dst) {
    int e = blockIdx.x * blockDim.x + threadIdx.x;
    if (e < NE) atomicAdd(&g_counts[dst[e]], 1);
}
__global__ void k_scan1() {
    __shared__ int warpTot[8];
    int b = blockIdx.x, t = threadIdx.x;
    int i = b * 256 + t;
    int c = (i < NN) ? g_counts[i] : 0;
    int lane = t & 31, wd = t >> 5;
    int v = c;
#pragma unroll
    for (int o = 16; o > 0; o >>= 1) v += __shfl_xor_sync(0xffffffffu, v, o);
    if (lane == 0) warpTot[wd] = v;
    __syncthreads();
    if (t == 0) {
        int s = 0;
#pragma unroll
        for (int j = 0; j < 8; j++) s += warpTot[j];
        g_blockSum[b] = s;
    }
}
__global__ void k_scan2() {
    __shared__ int warpTot[8];
    int t = threadIdx.x;   // 256
    int v = (t < NBLK) ? g_blockSum[t] : 0;
    int lane = t & 31, wd = t >> 5;
    int inc = v;
#pragma unroll
    for (int o = 1; o < 32; o <<= 1) {
        int u = __shfl_up_sync(0xffffffffu, inc, o);
        if (lane >= o) inc += u;
    }
    if (lane == 31) warpTot[wd] = inc;
    __syncthreads();
    if (t == 0) {
        int r = 0;
#pragma unroll
        for (int j = 0; j < 8; j++) { int x = warpTot[j]; warpTot[j] = r; r += x; }
        g_rowptr[NN] = r;
    }
    __syncthreads();
    int excl = inc - v + warpTot[wd];
    if (t < NBLK) g_blockOff[t] = excl;
}
__global__ void k_scan3() {
    __shared__ int warpTot[8];
    int b = blockIdx.x, t = threadIdx.x;
    int i = b * 256 + t;
    int c = (i < NN) ? g_counts[i] : 0;
    int lane = t & 31, wd = t >> 5;
    int inc = c;
#pragma unroll
    for (int o = 1; o < 32; o <<= 1) {
        int u = __shfl_up_sync(0xffffffffu, inc, o);
        if (lane >= o) inc += u;
    }
    if (lane == 31) warpTot[wd] = inc;
    __syncthreads();
    if (t == 0) {
        int r = 0;
#pragma unroll
        for (int j = 0; j < 8; j++) { int x = warpTot[j]; warpTot[j] = r; r += x; }
    }
    __syncthreads();
    int excl = inc - c + warpTot[wd] + g_blockOff[b];
    if (i < NN) {
        g_rowptr[i] = excl;
        g_cursor[i] = excl;
    }
}
__global__ void k_scatter(const int* __restrict__ src, const int* __restrict__ dst,
                          const float* __restrict__ vals) {
    int e = blockIdx.x * blockDim.x + threadIdx.x;
    if (e < NE) {
        int d = dst[e];
        int p = atomicAdd(&g_cursor[d], 1);
        g_csr_src[p] = src[e];
        g_csr_val[p] = vals[e];
    }
}

// ---------------- weight convert ----------------
__global__ void k_conv_W(const float* __restrict__ W, __half* __restrict__ B, int N) {
    __shared__ float tile[32][33];
    int k0 = blockIdx.y * 32, n0 = blockIdx.x * 32;
    int tx = threadIdx.x, ty = threadIdx.y;   // 32 x 8
    for (int r = ty; r < 32; r += 8)
        tile[r][tx] = W[(size_t)(k0 + r) * N + n0 + tx];
    __syncthreads();
    for (int r = ty; r < 32; r += 8)
        B[(size_t)(n0 + r) * KDIM + k0 + tx] = __float2half_rn(tile[tx][r]);
}

// ---------------- fp16 mma.sync GEMM (A fp16 via cp.async, or A fp32 via LDG+convert) ----------------
__device__ __forceinline__ void ldsm_x4(uint32_t* r, uint32_t a) {
    asm volatile("ldmatrix.sync.aligned.m8n8.x4.shared.b16 {%0,%1,%2,%3}, [%4];"
                 : "=r"(r[0]), "=r"(r[1]), "=r"(r[2]), "=r"(r[3]) : "r"(a));
}
__device__ __forceinline__ void mma_f16(float* c, const uint32_t* a, uint32_t b0, uint32_t b1) {
    asm volatile(
        "mma.sync.aligned.m16n8k16.row.col.f32.f16.f16.f32 "
        "{%0,%1,%2,%3}, {%4,%5,%6,%7}, {%8,%9}, {%0,%1,%2,%3};"
        : "+f"(c[0]), "+f"(c[1]), "+f"(c[2]), "+f"(c[3])
        : "r"(a[0]), "r"(a[1]), "r"(a[2]), "r"(a[3]), "r"(b0), "r"(b1));
}
__device__ __forceinline__ void cpa16(uint32_t saddr, const void* g, uint32_t sz) {
    asm volatile("cp.async.cg.shared.global [%0], [%1], 16, %2;"
                 :: "r"(saddr), "l"(g), "r"(sz));
}

template <bool AF32>
__global__ __launch_bounds__(512, 1)
void k_mma_gemm(const void* __restrict__ Ap, const __half* __restrict__ B,
                const float* __restrict__ bias, __half* __restrict__ C, int M, int N) {
    extern __shared__ __align__(1024) char smem[];
    const int A_SZ = 128 * 128;
    const int STG = A_SZ + 256 * 128;
    const int NCH = KDIM / 64;

    const __half* A16 = (const __half*)Ap;
    const float*  A32 = (const float*)Ap;

    uint32_t sbase = smem_u32(smem);
    int tid = threadIdx.x;
    int w = tid >> 5, lane = tid & 31;
    int m0 = blockIdx.y * 128, n0 = blockIdx.x * 256;
    int wm = (w >> 2) * 32, wn = (w & 3) * 64;

    // B loads via cp.async (both variants)
    auto load_B = [&](int ch) {
        int s = ch & 3;
        int kk = ch * 64;
        uint32_t bS = sbase + s * STG + A_SZ;
#pragma unroll
        for (int q = 0; q < 4; q++) {
            int u = tid + q * 512;
            int row = u >> 3, cb = u & 7;
            const __half* g = B + (size_t)(n0 + row) * KDIM + kk + cb * 8;
            cpa16(bS + SWZ(row * 128 + cb * 16), g, 16u);
        }
        asm volatile("cp.async.commit_group;" ::: "memory");
    };
    // A fp16 loads via cp.async
    auto load_A16 = [&](int ch) {
        int s = ch & 3;
        int kk = ch * 64;
        uint32_t aS = sbase + s * STG;
#pragma unroll
        for (int q = 0; q < 2; q++) {
            int u = tid + q * 512;
            int row = u >> 3, cb = u & 7;
            int gr = m0 + row;
            const __half* g = A16 + (size_t)gr * KDIM + kk + cb * 8;
            cpa16(aS + SWZ(row * 128 + cb * 16), g, (gr < M) ? 16u : 0u);
        }
    };
    // A fp32: register load + convert + STS
    float4 ar[2][2];
    auto load_A32 = [&](int ch) {
        int kk = ch * 64;
#pragma unroll
        for (int q = 0; q < 2; q++) {
            int u = tid + q * 512;
            int row = u >> 3, cb = u & 7;
            int gr = m0 + row;
            if (gr < M) {
                const float* g = A32 + (size_t)gr * KDIM + kk + cb * 8;
                ar[q][0] = *(const float4*)(g);
                ar[q][1] = *(const float4*)(g + 4);
            } else {
                ar[q][0] = make_float4(0.f, 0.f, 0.f, 0.f);
                ar[q][1] = make_float4(0.f, 0.f, 0.f, 0.f);
            }
        }
    };
    auto sts_A32 = [&](int ch) {
        int s = ch & 3;
#pragma unroll
        for (int q = 0; q < 2; q++) {
            int u = tid + q * 512;
            int row = u >> 3, cb = u & 7;
            __half2 h0 = __floats2half2_rn(ar[q][0].x, ar[q][0].y);
            __half2 h1 = __floats2half2_rn(ar[q][0].z, ar[q][0].w);
            __half2 h2 = __floats2half2_rn(ar[q][1].x, ar[q][1].y);
            __half2 h3 = __floats2half2_rn(ar[q][1].z, ar[q][1].w);
            uint4 pk = make_uint4(*(uint32_t*)&h0, *(uint32_t*)&h1,
                                  *(uint32_t*)&h2, *(uint32_t*)&h3);
            *(uint4*)(smem + s * STG + SWZ(row * 128 + cb * 16)) = pk;
        }
    };

    float c[2][8][4];
#pragma unroll
    for (int mi = 0; mi < 2; mi++)
#pragma unroll
        for (int ni = 0; ni < 8; ni++)
#pragma unroll
            for (int j = 0; j < 4; j++) c[mi][ni][j] = 0.0f;

    // prologue: 3 stages
    if (AF32) {
        load_A32(0); sts_A32(0); load_B(0);
        load_A32(1); sts_A32(1); load_B(1);
        load_A32(2); sts_A32(2); load_B(2);
    } else {
        load_A16(0); load_B(0);
        load_A16(1); load_B(1);
        load_A16(2); load_B(2);
    }

    for (int ch = 0; ch < NCH; ch++) {
        int rem = NCH - 1 - ch;
        if (rem >= 2)
            asm volatile("cp.async.wait_group 2;" ::: "memory");
        else if (rem == 1)
            asm volatile("cp.async.wait_group 1;" ::: "memory");
        else
            asm volatile("cp.async.wait_group 0;" ::: "memory");
        __syncthreads();

        // issue next-stage A LDGs early (fp32 variant) to hide latency under MMA
        bool pre = (ch + 3 < NCH);
        if (AF32 && pre) load_A32(ch + 3);

        uint32_t aS = sbase + (ch & 3) * STG;
        uint32_t bS = aS + A_SZ;
        int lrow = lane & 15;
        int lcol = (lane >> 4) * 16;
#pragma unroll
        for (int ks = 0; ks < 4; ks++) {
            uint32_t a[2][4], bb[4][4];
#pragma unroll
            for (int mi = 0; mi < 2; mi++)
                ldsm_x4(a[mi], aS + SWZ((wm + mi * 16 + lrow) * 128 + ks * 32 + lcol));
#pragma unroll
            for (int p = 0; p < 4; p++)
                ldsm_x4(bb[p], bS + SWZ((wn + p * 16 + lrow) * 128 + ks * 32 + lcol));
#pragma unroll
            for (int mi = 0; mi < 2; mi++)
#pragma unroll
                for (int ni = 0; ni < 8; ni++)
                    mma_f16(c[mi][ni], a[mi],
                            bb[ni >> 1][(ni & 1)], bb[ni >> 1][(ni & 1) + 2]);
        }
        if (pre) {
            if (AF32) {
                sts_A32(ch + 3);
            } else {
                load_A16(ch + 3);
            }
            load_B(ch + 3);
        }
    }

#pragma unroll
    for (int mi = 0; mi < 2; mi++) {
        int r0 = m0 + wm + mi * 16 + (lane >> 2);
        int r1 = r0 + 8;
#pragma unroll
        for (int ni = 0; ni < 8; ni++) {
            int col = n0 + wn + ni * 8 + (lane & 3) * 2;
            float b0 = bias[col], b1 = bias[col + 1];
            if (r0 < M) {
                __half2 v = __floats2half2_rn(c[mi][ni][0] + b0, c[mi][ni][1] + b1);
                *(__half2*)(C + (size_t)r0 * N + col) = v;
            }
            if (r1 < M) {
                __half2 v = __floats2half2_rn(c[mi][ni][2] + b0, c[mi][ni][3] + b1);
                *(__half2*)(C + (size_t)r1 * N + col) = v;
            }
        }
    }
}

// ---------------- SpMM 512-wide ----------------
__global__ void k_spmm512(const __half* __restrict__ A, __half* __restrict__ OutH) {
    int row = blockIdx.x;
    int t = threadIdx.x;               // 64
    int s = g_rowptr[row];
    int e = g_rowptr[row + 1];
    float acc[8];
#pragma unroll
    for (int j = 0; j < 8; j++) acc[j] = 0.f;
    for (int i = s; i < e; i++) {
        int sr = g_csr_src[i];
        float v = g_csr_val[i];
        uint4 raw = *(const uint4*)(A + (size_t)sr * 512 + t * 8);
        float2 f0 = __half22float2(*(__half2*)&raw.x);
        float2 f1 = __half22float2(*(__half2*)&raw.y);
        float2 f2 = __half22float2(*(__half2*)&raw.z);
        float2 f3 = __half22float2(*(__half2*)&raw.w);
        acc[0] = fmaf(v, f0.x, acc[0]); acc[1] = fmaf(v, f0.y, acc[1]);
        acc[2] = fmaf(v, f1.x, acc[2]); acc[3] = fmaf(v, f1.y, acc[3]);
        acc[4] = fmaf(v, f2.x, acc[4]); acc[5] = fmaf(v, f2.y, acc[5]);
        acc[6] = fmaf(v, f3.x, acc[6]); acc[7] = fmaf(v, f3.y, acc[7]);
    }
    __half2 h[4];
#pragma unroll
    for (int j = 0; j < 4; j++)
        h[j] = __floats2half2_rn(fmaxf(acc[j * 2], 0.f), fmaxf(acc[j * 2 + 1], 0.f));
    uint4 packed = make_uint4(*(uint32_t*)&h[0], *(uint32_t*)&h[1],
                              *(uint32_t*)&h[2], *(uint32_t*)&h[3]);
    *(uint4*)(OutH + (size_t)row * 512 + t * 8) = packed;
}

// ---------------- rank-k select + ssf sparsify ----------------
__global__ void k_thresh_ssf(const float* __restrict__ ssf, const float* __restrict__ sigma,
                             float* __restrict__ out_ssf, float* __restrict__ out_sigma) {
    __shared__ unsigned int hist[2048];
    __shared__ unsigned int s_prefix;
    __shared__ int s_rank;
    int t = threadIdx.x;  // 256
    if (t == 0) { s_prefix = 0u; s_rank = 8192; }
    __syncthreads();
    const int LO[3]  = {21, 10, 0};
    const int NB_[3] = {11, 11, 10};
    const int CHK[3] = {0, 21, 10};
    for (int p = 0; p < 3; p++) {
        for (int i = t; i < 2048; i += 256) hist[i] = 0u;
        __syncthreads();
        unsigned int pref = s_prefix;
        unsigned int mask = (1u << NB_[p]) - 1u;
        for (int i = t; i < NS * NC; i += 256) {
            unsigned int u = __float_as_uint(fabsf(ssf[i]));
            bool ok = (p == 0) ? true : ((u >> CHK[p]) == pref);
            if (ok) atomicAdd(&hist[(u >> LO[p]) & mask], 1u);
        }
        __syncthreads();
        if (t == 0) {
            int r = s_rank;
            unsigned int cum = 0;
            unsigned int nb = 1u << NB_[p];
            unsigned int b = 0;
            for (b = 0; b < nb; b++) {
                if (cum + hist[b] > (unsigned int)r) break;
                cum += hist[b];
            }
            s_rank = r - (int)cum;
            s_prefix = (s_prefix << NB_[p]) | b;
        }
        __syncthreads();
    }
    float thr = __uint_as_float(s_prefix);
    for (int i = t; i < NS * NC; i += 256) {
        float v = ssf[i];
        float o = (fabsf(v) >= thr) ? v : 0.0f;
        g_ssf_sp[i] = o;
        out_ssf[i] = o;
    }
    __syncthreads();
    if (t < NC) {
        float s = 0.f;
        for (int k = 0; k < NS; k++) {
            float v = g_ssf_sp[k * NC + t];
            s = fmaf(v, v, s);
        }
        g_colsq[t] = s;
        g_cn[t] = fmaxf(sqrtf(s), 1e-6f);
    }
    if (t == 0) out_sigma[0] = sigma[0];
}

// ---------------- fused: layer-3 spmm + out + spatial loss ----------------
__device__ __forceinline__ float warp_max(float v) {
#pragma unroll
    for (int o = 16; o > 0; o >>= 1) v = fmaxf(v, __shfl_xor_sync(0xffffffffu, v, o));
    return v;
}
__device__ __forceinline__ float warp_sum(float v) {
#pragma unroll
    for (int o = 16; o > 0; o >>= 1) v += __shfl_xor_sync(0xffffffffu, v, o);
    return v;
}

__global__ __launch_bounds__(64)
void k_spmm_loss(const __half* __restrict__ A, float* __restrict__ h_out,
                 float* __restrict__ out, float* __restrict__ loss) {
    __shared__ float sh[NS];
    __shared__ float redh[2], redm[2], redms[2], reds[2], redss[2];
    int row = blockIdx.x;
    int t = threadIdx.x;          // 64
    int lane = t & 31, wd = t >> 5;
    int s = g_rowptr[row];
    int e = g_rowptr[row + 1];
    float4 acc = make_float4(0.f, 0.f, 0.f, 0.f);
    for (int i = s; i < e; i++) {
        int sr = g_csr_src[i];
        float v = g_csr_val[i];
        uint2 raw = *(const uint2*)(A + (size_t)sr * NS + t * 4);
        float2 f01 = __half22float2(*(__half2*)&raw.x);
        float2 f23 = __half22float2(*(__half2*)&raw.y);
        acc.x = fmaf(v, f01.x, acc.x);
        acc.y = fmaf(v, f01.y, acc.y);
        acc.z = fmaf(v, f23.x, acc.z);
        acc.w = fmaf(v, f23.y, acc.w);
    }
    *(float4*)(h_out + (size_t)row * NS + t * 4) = acc;
    *(float4*)(sh + t * 4) = acc;
    float ssq = acc.x * acc.x + acc.y * acc.y + acc.z * acc.z + acc.w * acc.w;
    float hw = warp_sum(ssq);
    if (lane == 0) redh[wd] = hw;
    __syncthreads();
    float hh = redh[0] + redh[1];

    float dot = 0.f;
#pragma unroll 4
    for (int k = 0; k < NS; k++)
        dot = fmaf(sh[k], g_ssf_sp[k * NC + t], dot);

    float sq = hh - 2.0f * dot + g_colsq[t];
    float dist = -sqrtf(fmaxf(sq, 1e-12f));
    float hn = fmaxf(sqrtf(hh), 1e-6f);
    float sim = dot / (hn * g_cn[t]);

    float mdw = warp_max(dist);
    float msw = warp_max(sim);
    if (lane == 0) { redm[wd] = mdw; redms[wd] = msw; }
    __syncthreads();
    float md = fmaxf(redm[0], redm[1]);
    float ms = fmaxf(redms[0], redms[1]);
    float sdw = warp_sum(expf(dist - md));
    float ssw = warp_sum(expf(sim - ms));
    if (lane == 0) { reds[wd] = sdw; redss[wd] = ssw; }
    __syncthreads();
    float sd = reds[0] + reds[1];
    float ss = redss[0] + redss[1];

    float lsd = dist - md - logf(sd);
    float lss = sim - ms - logf(ss);
    out[(size_t)row * NC + t]  = dot;
    loss[(size_t)row * NC + t] = 0.5f * (lsd + lss);
}

// ---------------- launch ----------------
extern "C" void kernel_launch(void* const* d_in, const int* in_sizes, int n_in,
                              void* d_out, int out_size) {
    const float* x    = (const float*)d_in[0];
    const int*   src  = (const int*)d_in[1];
    const int*   dst  = (const int*)d_in[2];
    const float* vals = (const float*)d_in[3];
    const float* W1   = (const float*)d_in[4];
    const float* b1   = (const float*)d_in[5];
    const float* W2   = (const float*)d_in[6];
    const float* b2   = (const float*)d_in[7];
    const float* W3   = (const float*)d_in[8];
    const float* b3   = (const float*)d_in[9];
    const float* ssf  = (const float*)d_in[10];
    const float* sig  = (const float*)d_in[11];
    float* out = (float*)d_out;

    size_t o_out = 0;
    size_t o_ssf = (size_t)NN * NC;
    size_t o_h   = o_ssf + (size_t)NS * NC;
    size_t o_loss = o_h + (size_t)NN * NS;
    size_t o_sigma = o_loss + (size_t)NN * NC;

    __half* bufC = nullptr;
    __half *A = nullptr, *B1 = nullptr, *B2 = nullptr, *B3 = nullptr;
    cudaGetSymbolAddress((void**)&bufC, g_bufC);
    cudaGetSymbolAddress((void**)&A, g_A);
    cudaGetSymbolAddress((void**)&B1, g_B1);
    cudaGetSymbolAddress((void**)&B2, g_B2);
    cudaGetSymbolAddress((void**)&B3, g_B3);

    const int SMEM_MMA = 4 * (128 + 256) * 128;   // 196608
    cudaFuncSetAttribute(k_mma_gemm<true>, cudaFuncAttributeMaxDynamicSharedMemorySize, SMEM_MMA);
    cudaFuncSetAttribute(k_mma_gemm<false>, cudaFuncAttributeMaxDynamicSharedMemorySize, SMEM_MMA);

    dim3 wblk(32, 8);
    dim3 wgrid12(NH / 32, KDIM / 32);
    dim3 wgrid3(NS / 32, KDIM / 32);
    dim3 g12(NH / 256, (NN + 127) / 128);   // (2, 391)
    dim3 g3(NS / 256, (NN + 127) / 128);    // (1, 391)

    bool fork = g_res.ok;
    cudaStream_t s2 = fork ? g_res.s2 : (cudaStream_t)0;

    if (fork) {
        cudaEventRecord(g_res.eFork, 0);
        cudaStreamWaitEvent(s2, g_res.eFork, 0);
    }

    // ---- side stream: W1 convert, CSR build (wide scan), W2/W3, thresh ----
    k_conv_W<<<wgrid12, wblk, 0, s2>>>(W1, B1, NH);
    if (fork) cudaEventRecord(g_res.eW1, s2);
    k_zero_counts<<<(NN + 255) / 256, 256, 0, s2>>>();
    k_count<<<(NE + 255) / 256, 256, 0, s2>>>(dst);
    k_scan1<<<NBLK, 256, 0, s2>>>();
    k_scan2<<<1, 256, 0, s2>>>();
    k_scan3<<<NBLK, 256, 0, s2>>>();
    k_scatter<<<(NE + 255) / 256, 256, 0, s2>>>(src, dst, vals);
    if (fork) cudaEventRecord(g_res.eCSR, s2);
    k_conv_W<<<wgrid12, wblk, 0, s2>>>(W2, B2, NH);
    k_conv_W<<<wgrid3, wblk, 0, s2>>>(W3, B3, NS);
    if (fork) cudaEventRecord(g_res.eW23, s2);
    k_thresh_ssf<<<1, 256, 0, s2>>>(ssf, sig, out + o_ssf, out + o_sigma);
    if (fork) cudaEventRecord(g_res.eSSF, s2);

    // ---- main stream: GEMM1 reads fp32 x directly (fused convert) ----
    if (fork) cudaStreamWaitEvent(0, g_res.eW1, 0);
    k_mma_gemm<true><<<g12, 512, SMEM_MMA>>>(x, B1, b1, bufC, NN, NH);
    if (fork) cudaStreamWaitEvent(0, g_res.eCSR, 0);
    k_spmm512<<<NN, 64>>>(bufC, A);

    if (fork) cudaStreamWaitEvent(0, g_res.eW23, 0);
    k_mma_gemm<false><<<g12, 512, SMEM_MMA>>>(A, B2, b2, bufC, NN, NH);
    k_spmm512<<<NN, 64>>>(bufC, A);

    k_mma_gemm<false><<<g3, 512, SMEM_MMA>>>(A, B3, b3, bufC, NN, NS);
    if (fork) cudaStreamWaitEvent(0, g_res.eSSF, 0);
    k_spmm_loss<<<NN, 64>>>(bufC, out + o_h, out + o_out, out + o_loss);
}